// round 9
// baseline (speedup 1.0000x reference)
#include <cuda_runtime.h>
#include <cuda_fp16.h>
#include <cstdint>

// InteractionLayer: out[b, tri(i,j)] = dot(x[b,i,:], x[b,j,:]) for i<j
// x: [4096, 64, 128] fp32 -> out: [4096, 2016] fp32.
//
// sm_100 baseline PTX. mma.sync.m16n8k16 f16, fp32 accum.
// Single-term fp16 Gram (rel err ~3e-4 << 1e-3 gate, R5/R8-proven).
// Triangle skip: warp w needs tile-pairs tp >= w.
// R9: 4 batches/CTA, double-buffered smem, next-batch loads software-
// pipelined into the mma k-loop (skew 2) -> continuous DRAM stream.

#define NPAIR 2016
#define LDH   136                       // padded pitch in halves (272 B)
#define BUFB  (64 * LDH * 2)            // 17408 B per buffer
#define SM_TOTAL (2 * BUFB)             // 34816
#define NB    4                         // batches per CTA

__device__ __forceinline__ uint32_t smem_u32(const void* p) {
    uint32_t a;
    asm("{ .reg .u64 t; cvta.to.shared.u64 t, %1; cvt.u32.u64 %0, t; }"
        : "=r"(a) : "l"(p));
    return a;
}

__device__ __forceinline__ void ldsm4(uint32_t* r, uint32_t addr) {
    asm volatile("ldmatrix.sync.aligned.m8n8.x4.shared.b16 {%0,%1,%2,%3}, [%4];"
                 : "=r"(r[0]), "=r"(r[1]), "=r"(r[2]), "=r"(r[3]) : "r"(addr));
}
__device__ __forceinline__ void mma16816(float* d, const uint32_t* a,
                                         const uint32_t* b) {
    asm volatile(
        "mma.sync.aligned.m16n8k16.row.col.f32.f16.f16.f32 "
        "{%0,%1,%2,%3}, {%4,%5,%6,%7}, {%8,%9}, {%0,%1,%2,%3};"
        : "+f"(d[0]), "+f"(d[1]), "+f"(d[2]), "+f"(d[3])
        : "r"(a[0]), "r"(a[1]), "r"(a[2]), "r"(a[3]), "r"(b[0]), "r"(b[1]));
}

__global__ __launch_bounds__(128)
void gram_tri_kernel(const float* __restrict__ x, float* __restrict__ out) {
    extern __shared__ char smem[];
    const int tid = threadIdx.x;
    const int w   = tid >> 5;
    const int l   = tid & 31;
    const int kcol = (tid & 31) << 2;       // 0..124 (col within 128-elem row)

    const uint32_t sb = smem_u32(smem);
    const float4* xin =
        reinterpret_cast<const float4*>(x) + (size_t)blockIdx.x * (NB * 2048);

    // fragment address offsets (relative to buffer base), R8-proven layout
    const uint32_t aOff =
        (uint32_t)(((w * 16 + (l & 15)) * LDH + ((l >> 4) << 3)) << 1);
    const uint32_t bOff =
        (uint32_t)((((l & 7) + (l & 16) / 2) * LDH + (l & 8)) << 1);

    // epilogue constants (R8-proven)
    const int i0 = w * 16 + (l >> 2);
    const int i1 = i0 + 8;
    const int c0 = (l & 3) * 2;
    const int eb0 = (63 * i0 - (i0 * (i0 - 1)) / 2 - i0 - 1) + c0;
    const int eb1 = (63 * i1 - (i1 * (i1 - 1)) / 2 - i1 - 1) + c0;
    const int th0 = i0 - c0;
    const int th1 = i1 - c0;

    // ---- prologue: batch 0 -> buffer 0, max MLP ----
    {
        float4 v[16];
#pragma unroll
        for (int it = 0; it < 16; ++it) v[it] = xin[tid + it * 128];
        __half2* b0 = reinterpret_cast<__half2*>(smem);
#pragma unroll
        for (int it = 0; it < 16; ++it) {
            const int o = ((w + 4 * it) * LDH + kcol) >> 1;
            b0[o]     = __floats2half2_rn(v[it].x, v[it].y);
            b0[o + 1] = __floats2half2_rn(v[it].z, v[it].w);
        }
    }
    __syncthreads();

#pragma unroll
    for (int bi = 0; bi < NB; ++bi) {
        const uint32_t bb = sb + (uint32_t)(bi & 1) * BUFB;
        const uint32_t aH = bb + aOff;
        const uint32_t bH = bb + bOff;
        __half2* nb =
            reinterpret_cast<__half2*>(smem + ((bi + 1) & 1) * BUFB);
        const float4* nxt = xin + (bi + 1) * 2048;
        const bool ld = (bi < NB - 1);

        float dg[32];
#pragma unroll
        for (int i = 0; i < 32; ++i) dg[i] = 0.f;

        float4 pend[2][2];   // two pipeline slots, one row-pair each

#pragma unroll
        for (int s = 0; s < 8; ++s) {
            if (ld) {
                if (s >= 2) {
                    const float4 va = pend[s & 1][0];
                    const float4 vb = pend[s & 1][1];
                    const int s2 = s - 2;
                    const int o0 = ((w + 8 * s2) * LDH + kcol) >> 1;
                    nb[o0]     = __floats2half2_rn(va.x, va.y);
                    nb[o0 + 1] = __floats2half2_rn(va.z, va.w);
                    const int o1 = ((w + 8 * s2 + 4) * LDH + kcol) >> 1;
                    nb[o1]     = __floats2half2_rn(vb.x, vb.y);
                    nb[o1 + 1] = __floats2half2_rn(vb.z, vb.w);
                }
                pend[s & 1][0] = nxt[tid + (2 * s) * 128];
                pend[s & 1][1] = nxt[tid + (2 * s + 1) * 128];
            }
            uint32_t ah[4];
            ldsm4(ah, aH + s * 32);
#pragma unroll
            for (int tp = 0; tp < 4; ++tp) {        // n-tiles 2tp, 2tp+1
                if (tp >= w) {                      // triangle skip
                    uint32_t bh[4];
                    ldsm4(bh, bH + (uint32_t)(tp * 16 * LDH * 2) + s * 32);
                    mma16816(dg + tp * 8,     ah, bh);
                    mma16816(dg + tp * 8 + 4, ah, bh + 2);
                }
            }
        }

        if (ld) {   // drain pipeline: pairs 6 and 7
#pragma unroll
            for (int q = 0; q < 2; ++q) {
                const float4 va = pend[q][0];
                const float4 vb = pend[q][1];
                const int s2 = 6 + q;
                const int o0 = ((w + 8 * s2) * LDH + kcol) >> 1;
                nb[o0]     = __floats2half2_rn(va.x, va.y);
                nb[o0 + 1] = __floats2half2_rn(va.z, va.w);
                const int o1 = ((w + 8 * s2 + 4) * LDH + kcol) >> 1;
                nb[o1]     = __floats2half2_rn(vb.x, vb.y);
                nb[o1 + 1] = __floats2half2_rn(vb.z, vb.w);
            }
        }

        // ---- epilogue: hoisted bases + threshold predicates ----
        {
            float* ob = out + (size_t)(blockIdx.x * NB + bi) * NPAIR;
            float* p0 = ob + eb0;
            float* p1 = ob + eb1;
#pragma unroll
            for (int t = 0; t < 8; ++t) {
                const int jt = t * 8;
                if (jt >  th0) p0[jt]     = dg[t * 4 + 0];
                if (jt >= th0) p0[jt + 1] = dg[t * 4 + 1];
                if (jt >  th1) p1[jt]     = dg[t * 4 + 2];
                if (jt >= th1) p1[jt + 1] = dg[t * 4 + 3];
            }
        }

        __syncthreads();   // next buffer fully written; this buffer fully read
    }
}

extern "C" void kernel_launch(void* const* d_in, const int* in_sizes, int n_in,
                              void* d_out, int out_size) {
    const float* x = (const float*)d_in[0];
    float* out = (float*)d_out;
    cudaFuncSetAttribute(gram_tri_kernel,
                         cudaFuncAttributeMaxDynamicSharedMemorySize, SM_TOTAL);
    gram_tri_kernel<<<1024, 128, SM_TOTAL>>>(x, out);
}

// round 12
// speedup vs baseline: 1.0987x; 1.0987x over previous
#include <cuda_runtime.h>
#include <cuda_fp16.h>
#include <cstdint>

// InteractionLayer: out[b, tri(i,j)] = dot(x[b,i,:], x[b,j,:]) for i<j
// x: [4096, 64, 128] fp32 -> out: [4096, 2016] fp32.
//
// sm_100 baseline PTX. mma.sync.m16n8k16 f16, fp32 accum.
// Single-term fp16 Gram (rel err ~3e-4 << 1e-3 gate, R5/R8-proven).
// Triangle skip: warp w needs tile-pairs tp >= w.
// R10/R12: R8 structure (1 batch/CTA, grid 4096) + smem-staged epilogue:
// dg -> padded gram buffer (stride 66, reusing the input buffer), then
// coalesced row-wise copy-out. Replaces ~500 scattered-STG wavefronts/warp
// with ~90 (L1 was the top pipe at 60%).

#define NPAIR 2016
#define LDH   136                       // padded pitch in halves (272 B)
#define SM_TOTAL (64 * LDH * 2)         // 17408 bytes (>= 64*66*4 = 16896)

__device__ __forceinline__ uint32_t smem_u32(const void* p) {
    uint32_t a;
    asm("{ .reg .u64 t; cvta.to.shared.u64 t, %1; cvt.u32.u64 %0, t; }"
        : "=r"(a) : "l"(p));
    return a;
}

__device__ __forceinline__ void ldsm4(uint32_t* r, uint32_t addr) {
    asm volatile("ldmatrix.sync.aligned.m8n8.x4.shared.b16 {%0,%1,%2,%3}, [%4];"
                 : "=r"(r[0]), "=r"(r[1]), "=r"(r[2]), "=r"(r[3]) : "r"(addr));
}
__device__ __forceinline__ void mma16816(float* d, const uint32_t* a,
                                         const uint32_t* b) {
    asm volatile(
        "mma.sync.aligned.m16n8k16.row.col.f32.f16.f16.f32 "
        "{%0,%1,%2,%3}, {%4,%5,%6,%7}, {%8,%9}, {%0,%1,%2,%3};"
        : "+f"(d[0]), "+f"(d[1]), "+f"(d[2]), "+f"(d[3])
        : "r"(a[0]), "r"(a[1]), "r"(a[2]), "r"(a[3]), "r"(b[0]), "r"(b[1]));
}

__global__ __launch_bounds__(128)
void gram_tri_kernel(const float* __restrict__ x, float* __restrict__ out) {
    extern __shared__ char smem[];
    const int tid = threadIdx.x;
    const int w   = tid >> 5;
    const int l   = tid & 31;

    // ---- load one batch (8192 floats), convert fp16, padded smem ----
    {
        const float4* xin =
            reinterpret_cast<const float4*>(x) + (size_t)blockIdx.x * 2048;
        __half2* xh = reinterpret_cast<__half2*>(smem);
        const int k = (tid & 31) << 2;          // fixed per thread
#pragma unroll
        for (int it = 0; it < 16; ++it) {
            const float4 v = xin[tid + it * 128];
            const int row = w + it * 4;         // 0..63
            const int o = (row * LDH + k) >> 1; // __half2 index
            xh[o]     = __floats2half2_rn(v.x, v.y);
            xh[o + 1] = __floats2half2_rn(v.z, v.w);
        }
    }
    __syncthreads();

    const uint32_t sb = smem_u32(smem);

    // A fragment (warp's 16 rows), ldmatrix.x4:
    // lanes 0-15 -> 16 rows (k0-7), lanes 16-31 -> same rows (k8-15).
    const uint32_t aH =
        sb + (uint32_t)(((w * 16 + (l & 15)) * LDH + ((l >> 4) << 3)) << 1);

    // B fragment via ldmatrix.x4 covering TWO n-tiles:
    // lanes 0-7: even tile k0-7 | 8-15: even tile k8-15
    // lanes 16-23: odd tile k0-7 | 24-31: odd tile k8-15
    const uint32_t bH =
        sb + (uint32_t)((((l & 7) + (l & 16) / 2) * LDH + (l & 8)) << 1);

    float dg[32];
#pragma unroll
    for (int i = 0; i < 32; ++i) dg[i] = 0.f;

#pragma unroll
    for (int k = 0; k < 8; ++k) {
        uint32_t ah[4];
        ldsm4(ah, aH + k * 32);
#pragma unroll
        for (int tp = 0; tp < 4; ++tp) {        // n-tiles 2tp, 2tp+1
            if (tp >= w) {                      // triangle skip (warp-uniform)
                uint32_t bh[4];
                ldsm4(bh, bH + (uint32_t)(tp * 16 * LDH * 2) + k * 32);
                mma16816(dg + tp * 8,     ah, bh);      // even tile
                mma16816(dg + tp * 8 + 4, ah, bh + 2);  // odd tile
            }
        }
    }

    __syncthreads();    // all warps done reading xh; reuse buffer for gram

    // ---- stage: dg -> gram smem, stride 66 (even => float2-aligned,
    //      banks rotate by 2 per row; <=4-way STS conflicts) ----
    {
        float* gs = reinterpret_cast<float*>(smem);
        const int i0 = w * 16 + (l >> 2);
        const int c0 = (l & 3) * 2;
#pragma unroll
        for (int t = 0; t < 8; ++t) {
            *reinterpret_cast<float2*>(gs + i0 * 66 + t * 8 + c0) =
                make_float2(dg[t * 4 + 0], dg[t * 4 + 1]);
            *reinterpret_cast<float2*>(gs + (i0 + 8) * 66 + t * 8 + c0) =
                make_float2(dg[t * 4 + 2], dg[t * 4 + 3]);
        }
    }
    __syncthreads();

    // ---- copy-out: rows striped across warps, contiguous stores ----
    // out index for (i,j), j>i: 63i - i(i-1)/2 + (j-i-1); row i has 63-i
    // entries starting at tri(i) = 63i - i(i-1)/2, source gs[i*66 + i+1 ...].
    {
        float* ob = out + (size_t)blockIdx.x * NPAIR;
        const float* gs = reinterpret_cast<const float*>(smem);
#pragma unroll
        for (int ri = 0; ri < 16; ++ri) {
            const int i  = w + ri * 4;          // 0..63 striped over warps
            const int ni = 63 - i;
            const float* src = gs + i * 66 + i + 1;
            float* dst = ob + 63 * i - (i * (i - 1)) / 2;
            if (l < ni)      dst[l]      = src[l];
            if (l + 32 < ni) dst[l + 32] = src[l + 32];
        }
    }
}

extern "C" void kernel_launch(void* const* d_in, const int* in_sizes, int n_in,
                              void* d_out, int out_size) {
    const float* x = (const float*)d_in[0];
    float* out = (float*)d_out;
    cudaFuncSetAttribute(gram_tri_kernel,
                         cudaFuncAttributeMaxDynamicSharedMemorySize, SM_TOTAL);
    gram_tri_kernel<<<4096, 128, SM_TOTAL>>>(x, out);
}